// round 1
// baseline (speedup 1.0000x reference)
#include <cuda_runtime.h>
#include <math_constants.h>

// Problem shape (fixed): x[8][4096][1024] fp32, cumulative logaddexp along axis 1.
#define BB 8
#define TT 4096
#define CC 1024

#define SEG 32                   // segments per sequence (per block)
#define SEG_LEN (TT / SEG)       // 128 elements per segment
#define LANES 8                  // float4 lanes -> 32 channels per block
#define CH_PER_BLOCK (LANES * 4) // 32
#define THREADS (LANES * SEG)    // 256
#define NBLOCKS (BB * (CC / CH_PER_BLOCK)) // 256

// Running logsumexp state in (m, s) form: value = m + ln(s).
// Branchless update with new sample x:
//   if x > m : s' = s*exp(m-x) + 1 ; m' = x
//   else     : s' = s + exp(x-m)   ; m' = m
// Handles m = -inf seed exactly (exp(-inf) = 0).
__device__ __forceinline__ void upd(float& m, float& s, float x) {
    float mx = fmaxf(m, x);
    float mn = fminf(m, x);
    float t  = __expf(mn - mx);     // FMUL + MUFU.EX2
    bool  g  = (x > m);
    float mult = g ? t    : 1.0f;
    float add  = g ? 1.0f : t;
    s = __fmaf_rn(s, mult, add);
    m = mx;
}

// Full logaddexp for the small cross-segment prefix scan.
__device__ __forceinline__ float la(float a, float b) {
    float mx = fmaxf(a, b);
    float mn = fminf(a, b);
    return mx + __logf(1.0f + __expf(mn - mx));
}

__global__ __launch_bounds__(THREADS)
void lcse_kernel(const float* __restrict__ x, float* __restrict__ out) {
    __shared__ float4 tot[SEG][LANES];   // per-(segment, 4-channel) totals / prefixes

    const int tid  = threadIdx.x;
    const int lane = tid & (LANES - 1);  // which float4 within the 32-channel tile
    const int seg  = tid / LANES;        // which t-segment
    const int blk  = blockIdx.x;
    const int b    = blk >> 5;           // / (CC / CH_PER_BLOCK) == /32
    const int ct   = blk & 31;

    const size_t base = ((size_t)b * TT + (size_t)seg * SEG_LEN) * CC
                        + (size_t)ct * CH_PER_BLOCK + (size_t)lane * 4;
    const float4* __restrict__ px = reinterpret_cast<const float4*>(x + base);
    float4* __restrict__ po       = reinterpret_cast<float4*>(out + base);
    const int STR = CC / 4;              // 256 float4 per t-step (4 KB)

    // ---- Sweep 1: per-segment logsumexp totals (no outputs, 1 EX2/elem) ----
    float m0 = -CUDART_INF_F, m1 = -CUDART_INF_F, m2 = -CUDART_INF_F, m3 = -CUDART_INF_F;
    float s0 = 0.f, s1 = 0.f, s2 = 0.f, s3 = 0.f;
    #pragma unroll 4
    for (int i = 0; i < SEG_LEN; ++i) {
        float4 v = px[i * STR];
        upd(m0, s0, v.x); upd(m1, s1, v.y); upd(m2, s2, v.z); upd(m3, s3, v.w);
    }
    float4 tv;
    tv.x = __fmaf_rn(__log2f(s0), CUDART_LN2_F, m0);
    tv.y = __fmaf_rn(__log2f(s1), CUDART_LN2_F, m1);
    tv.z = __fmaf_rn(__log2f(s2), CUDART_LN2_F, m2);
    tv.w = __fmaf_rn(__log2f(s3), CUDART_LN2_F, m3);
    tot[seg][lane] = tv;
    __syncthreads();

    // ---- Tiny exclusive prefix scan over SEG totals per channel ----
    if (seg == 0) {
        float4 p = make_float4(-CUDART_INF_F, -CUDART_INF_F, -CUDART_INF_F, -CUDART_INF_F);
        #pragma unroll
        for (int k = 0; k < SEG; ++k) {
            float4 t = tot[k][lane];
            tot[k][lane] = p;            // exclusive prefix
            p.x = la(p.x, t.x);
            p.y = la(p.y, t.y);
            p.z = la(p.z, t.z);
            p.w = la(p.w, t.w);
        }
    }
    __syncthreads();

    // ---- Sweep 2: rescan seeded with segment prefix, emit outputs ----
    float4 pr = tot[seg][lane];
    m0 = pr.x; m1 = pr.y; m2 = pr.z; m3 = pr.w;
    s0 = s1 = s2 = s3 = 1.0f;            // value = m + ln(1) = prefix (exact for -inf too)
    #pragma unroll 4
    for (int i = 0; i < SEG_LEN; ++i) {
        float4 v = px[i * STR];
        upd(m0, s0, v.x); upd(m1, s1, v.y); upd(m2, s2, v.z); upd(m3, s3, v.w);
        float4 o;
        o.x = __fmaf_rn(__log2f(s0), CUDART_LN2_F, m0);
        o.y = __fmaf_rn(__log2f(s1), CUDART_LN2_F, m1);
        o.z = __fmaf_rn(__log2f(s2), CUDART_LN2_F, m2);
        o.w = __fmaf_rn(__log2f(s3), CUDART_LN2_F, m3);
        po[i * STR] = o;
    }
}

extern "C" void kernel_launch(void* const* d_in, const int* in_sizes, int n_in,
                              void* d_out, int out_size) {
    (void)in_sizes; (void)n_in; (void)out_size;
    const float* x = (const float*)d_in[0];
    float* out = (float*)d_out;
    lcse_kernel<<<NBLOCKS, THREADS>>>(x, out);
}

// round 2
// speedup vs baseline: 1.3525x; 1.3525x over previous
#include <cuda_runtime.h>
#include <math_constants.h>

// x[8][4096][1024] fp32, cumulative logaddexp along axis 1 (t).
#define BB 8
#define TT 4096
#define CC 1024

#define LANES 4                       // float4 lanes per block -> 16 channels
#define CH_PER_BLOCK (LANES * 4)      // 16
#define SEG_T 64                      // threads along t
#define THREADS (LANES * SEG_T)       // 256
#define T_LOC 8                       // t-elements per thread per chunk (register buffer)
#define T_CHUNK (SEG_T * T_LOC)       // 512
#define N_CHUNKS (TT / T_CHUNK)       // 8
#define NBLOCKS (BB * (CC / CH_PER_BLOCK)) // 512

#define NEG_INF (-CUDART_INF_F)

// Running logsumexp state in (m, s) form: value = m + ln(s).
// Branchless; exact for the (m=-inf, s in {0,1}) seeds: exp(-inf)=0.
__device__ __forceinline__ void upd(float& m, float& s, float x) {
    float mx = fmaxf(m, x);
    float mn = fminf(m, x);
    float t  = __expf(mn - mx);
    bool  g  = (x > m);
    float mult = g ? t    : 1.0f;
    float add  = g ? 1.0f : t;
    s = __fmaf_rn(s, mult, add);
    m = mx;
}

// Guarded logaddexp for prefix combines: la(-inf,-inf) = -inf (avoid inf-inf NaN).
__device__ __forceinline__ float la_g(float a, float b) {
    float mx = fmaxf(a, b);
    float mn = fminf(a, b);
    float d  = mn - mx;
    d = (mn == mx) ? 0.0f : d;           // equal (incl. both -inf): exp(0)=1 path
    return mx + __logf(1.0f + __expf(d));
}

__device__ __forceinline__ float4 la4(float4 a, float4 b) {
    float4 r;
    r.x = la_g(a.x, b.x); r.y = la_g(a.y, b.y);
    r.z = la_g(a.z, b.z); r.w = la_g(a.w, b.w);
    return r;
}

__device__ __forceinline__ float finish(float m, float s) {
    return __fmaf_rn(__log2f(s), CUDART_LN2_F, m);   // m + ln(s)
}

__global__ __launch_bounds__(THREADS, 3)
void lcse_kernel(const float* __restrict__ x, float* __restrict__ out) {
    __shared__ float4 tot[2][SEG_T][LANES];   // double-buffered scan array (8 KB)

    const int tid  = threadIdx.x;
    const int lane = tid & (LANES - 1);
    const int ts   = tid / LANES;             // 0..63, position along t within chunk
    const int blk  = blockIdx.x;
    const int b    = blk / (CC / CH_PER_BLOCK);
    const int ct   = blk % (CC / CH_PER_BLOCK);

    const size_t col = (size_t)ct * CH_PER_BLOCK + (size_t)lane * 4;
    const float4* __restrict__ px = reinterpret_cast<const float4*>(x + (size_t)b * TT * CC + col);
    float4* __restrict__ po       = reinterpret_cast<float4*>(out + (size_t)b * TT * CC + col);
    const int STR = CC / 4;                   // float4 stride per t-step

    float4 carry = make_float4(NEG_INF, NEG_INF, NEG_INF, NEG_INF);

    for (int c = 0; c < N_CHUNKS; ++c) {
        const int t0 = c * T_CHUNK + ts * T_LOC;

        // ---- Load chunk slice into registers (8 x LDG.128, high MLP) ----
        float4 v[T_LOC];
        #pragma unroll
        for (int j = 0; j < T_LOC; ++j)
            v[j] = px[(size_t)(t0 + j) * STR];

        // ---- Pass A: thread-local logsumexp total over T_LOC elements ----
        float m0 = NEG_INF, m1 = NEG_INF, m2 = NEG_INF, m3 = NEG_INF;
        float s0 = 0.f, s1 = 0.f, s2 = 0.f, s3 = 0.f;
        #pragma unroll
        for (int j = 0; j < T_LOC; ++j) {
            upd(m0, s0, v[j].x); upd(m1, s1, v[j].y);
            upd(m2, s2, v[j].z); upd(m3, s3, v[j].w);
        }
        float4 tv;
        tv.x = finish(m0, s0); tv.y = finish(m1, s1);
        tv.z = finish(m2, s2); tv.w = finish(m3, s3);
        tot[0][ts][lane] = tv;
        __syncthreads();

        // ---- Kogge-Stone inclusive scan over the 64 thread totals ----
        int src = 0;
        float4 val = tv;
        #pragma unroll
        for (int d = 1; d < SEG_T; d <<= 1) {
            if (ts >= d) {
                float4 o = tot[src][ts - d][lane];
                val = la4(o, val);
            }
            tot[src ^ 1][ts][lane] = val;
            __syncthreads();
            src ^= 1;
        }
        // src == 0 again (6 toggles); tot[src] holds the inclusive scan.
        float4 total = tot[src][SEG_T - 1][lane];
        float4 excl  = (ts == 0)
                       ? make_float4(NEG_INF, NEG_INF, NEG_INF, NEG_INF)
                       : tot[src][ts - 1][lane];
        float4 p = la4(carry, excl);      // global exclusive prefix for this thread
        carry    = la4(carry, total);     // running carry for next chunk (replicated)
        __syncthreads();                  // protect tot[] reads before next chunk's writes

        // ---- Pass B: seeded rescan of registers, emit outputs ----
        m0 = p.x; m1 = p.y; m2 = p.z; m3 = p.w;
        s0 = s1 = s2 = s3 = 1.0f;         // state value == p (exact for p = -inf too)
        #pragma unroll
        for (int j = 0; j < T_LOC; ++j) {
            upd(m0, s0, v[j].x); upd(m1, s1, v[j].y);
            upd(m2, s2, v[j].z); upd(m3, s3, v[j].w);
            float4 o;
            o.x = finish(m0, s0); o.y = finish(m1, s1);
            o.z = finish(m2, s2); o.w = finish(m3, s3);
            po[(size_t)(t0 + j) * STR] = o;
        }
    }
}

extern "C" void kernel_launch(void* const* d_in, const int* in_sizes, int n_in,
                              void* d_out, int out_size) {
    (void)in_sizes; (void)n_in; (void)out_size;
    const float* x = (const float*)d_in[0];
    float* out = (float*)d_out;
    lcse_kernel<<<NBLOCKS, THREADS>>>(x, out);
}